// round 1
// baseline (speedup 1.0000x reference)
#include <cuda_runtime.h>

#define CIN   32
#define COUT  32
#define KTAP  27
#define WELEMS (KTAP * CIN * COUT)   // 27648 floats = 110592 bytes
#define MAX_N 131072
#define BN_EPS 1e-3f

// Scratch (device globals — no allocation allowed in kernel_launch)
__device__ float g_xT[(size_t)MAX_N * CIN];        // x transposed to [N, Cin]
__device__ float g_y[(size_t)COUT * MAX_N];        // pre-BN result, [Cout, N]
__device__ float g_params[2 * COUT];               // scale[32], shift[32]

// ---------------- packed f32x2 helpers (Blackwell FFMA2) ----------------
static __device__ __forceinline__ unsigned long long pack2(float a, float b) {
    unsigned long long r;
    asm("mov.b64 %0, {%1, %2};" : "=l"(r) : "f"(a), "f"(b));
    return r;
}
static __device__ __forceinline__ void unpack2(unsigned long long v, float& a, float& b) {
    asm("mov.b64 {%0, %1}, %2;" : "=f"(a), "=f"(b) : "l"(v));
}
static __device__ __forceinline__ void ffma2(unsigned long long& d,
                                             unsigned long long a,
                                             unsigned long long b) {
    asm("fma.rn.f32x2 %0, %1, %2, %0;" : "+l"(d) : "l"(a), "l"(b));
}

// ---------------- kernel 0: transpose [Cin, N] -> [N, Cin] ----------------
__global__ void transpose_kernel(const float* __restrict__ in, int N) {
    __shared__ float tile[32][33];
    int nb = blockIdx.x * 32;
    int tx = threadIdx.x;   // 0..31
    int ty = threadIdx.y;   // 0..7
#pragma unroll
    for (int j = 0; j < 4; ++j) {
        int c = ty + j * 8;
        int n = nb + tx;
        if (n < N) tile[c][tx] = in[(size_t)c * N + n];
    }
    __syncthreads();
#pragma unroll
    for (int j = 0; j < 4; ++j) {
        int n = nb + ty + j * 8;
        int c = tx;
        if (n < N) g_xT[(size_t)n * CIN + c] = tile[c][ty + j * 8];
    }
}

// ---------------- kernel 1: gather + GEMM (fma pipe bound) ----------------
__global__ void __launch_bounds__(256, 2)
conv_kernel(const int* __restrict__ neigh, const float* __restrict__ w, int N) {
    extern __shared__ float ws[];   // [KTAP][CIN][COUT] = 27648 floats
    for (int i = threadIdx.x; i < WELEMS; i += blockDim.x) ws[i] = w[i];
    __syncthreads();

    const int lane    = threadIdx.x & 31;
    const int gwarp   = blockIdx.x * (blockDim.x >> 5) + (threadIdx.x >> 5);
    const int nwarps  = gridDim.x * (blockDim.x >> 5);
    const int nchunks = (N + 31) >> 5;

    for (int ch = gwarp; ch < nchunks; ch += nwarps) {
        const int n = ch * 32 + lane;
        if (n >= N) continue;   // N%32==0 for this problem, guard anyway

        unsigned long long acc[16];   // acc[p] holds channels (2p, 2p+1)
#pragma unroll
        for (int j = 0; j < 16; ++j) acc[j] = 0ull;

        const int* nrow = neigh + (size_t)n * KTAP;
        int idx = nrow[0];
#pragma unroll 1
        for (int k = 0; k < KTAP; ++k) {
            const int nidx = (k < KTAP - 1) ? nrow[k + 1] : 0;
            const float4* xr = reinterpret_cast<const float4*>(g_xT + (size_t)idx * CIN);
            const float* wk = ws + k * (CIN * COUT);
#pragma unroll
            for (int q = 0; q < 8; ++q) {
                float4 xv = xr[q];
#pragma unroll
                for (int cc = 0; cc < 4; ++cc) {
                    float xs = (cc == 0) ? xv.x : (cc == 1) ? xv.y : (cc == 2) ? xv.z : xv.w;
                    unsigned long long xp = pack2(xs, xs);
                    const ulonglong2* wrow =
                        reinterpret_cast<const ulonglong2*>(wk + (q * 4 + cc) * COUT);
#pragma unroll
                    for (int j = 0; j < 8; ++j) {
                        ulonglong2 wv = wrow[j];    // LDS.128: channels 4j..4j+3
                        ffma2(acc[2 * j],     xp, wv.x);
                        ffma2(acc[2 * j + 1], xp, wv.y);
                    }
                }
            }
            idx = nidx;
        }

        // store y in output-friendly [Cout, N] layout (coalesced per channel)
#pragma unroll
        for (int j = 0; j < 16; ++j) {
            float lo, hi;
            unpack2(acc[j], lo, hi);
            g_y[(size_t)(2 * j)     * N + n] = lo;
            g_y[(size_t)(2 * j + 1) * N + n] = hi;
        }
    }
}

// ---------------- kernel 2: per-channel BN stats -> scale/shift ----------------
__global__ void stats_kernel(const float* __restrict__ gamma,
                             const float* __restrict__ beta, int N) {
    const int d = blockIdx.x;
    const float* yd = g_y + (size_t)d * N;
    float s = 0.f, q = 0.f;
    for (int i = threadIdx.x; i < N; i += blockDim.x) {
        float v = yd[i];
        s += v;
        q += v * v;
    }
#pragma unroll
    for (int o = 16; o; o >>= 1) {
        s += __shfl_xor_sync(~0u, s, o);
        q += __shfl_xor_sync(~0u, q, o);
    }
    __shared__ float ss[32], sq[32];
    int wid = threadIdx.x >> 5, lane = threadIdx.x & 31;
    if (lane == 0) { ss[wid] = s; sq[wid] = q; }
    __syncthreads();
    if (threadIdx.x < 32) {
        int nw = blockDim.x >> 5;
        s = (threadIdx.x < nw) ? ss[threadIdx.x] : 0.f;
        q = (threadIdx.x < nw) ? sq[threadIdx.x] : 0.f;
#pragma unroll
        for (int o = 16; o; o >>= 1) {
            s += __shfl_xor_sync(~0u, s, o);
            q += __shfl_xor_sync(~0u, q, o);
        }
        if (threadIdx.x == 0) {
            float mean = s / (float)N;
            float var  = q / (float)N - mean * mean;
            float inv  = rsqrtf(var + BN_EPS);
            float sc   = gamma[d] * inv;
            g_params[d]        = sc;
            g_params[COUT + d] = beta[d] - mean * sc;
        }
    }
}

// ---------------- kernel 3: normalize + write output ----------------
__global__ void norm_kernel(float* __restrict__ out, int N) {
    int i = blockIdx.x * blockDim.x + threadIdx.x;
    int total4 = (COUT * N) >> 2;   // N % 4 == 0
    if (i >= total4) return;
    int d = (i << 2) / N;
    float4 v = reinterpret_cast<const float4*>(g_y)[i];
    float sc = g_params[d], sh = g_params[COUT + d];
    v.x = v.x * sc + sh;
    v.y = v.y * sc + sh;
    v.z = v.z * sc + sh;
    v.w = v.w * sc + sh;
    reinterpret_cast<float4*>(out)[i] = v;
}

// ---------------- launch ----------------
extern "C" void kernel_launch(void* const* d_in, const int* in_sizes, int n_in,
                              void* d_out, int out_size) {
    const float* data_in = (const float*)d_in[0];   // [1, Cin, N, 1]
    const int*   neigh   = (const int*)d_in[1];     // [N, 27]
    const float* weight  = (const float*)d_in[2];   // [27, Cin, Cout]
    const float* gamma   = (const float*)d_in[3];   // [Cout]
    const float* beta    = (const float*)d_in[4];   // [Cout]
    float*       out     = (float*)d_out;

    const int N = in_sizes[0] / CIN;

    cudaFuncSetAttribute(conv_kernel,
                         cudaFuncAttributeMaxDynamicSharedMemorySize,
                         WELEMS * (int)sizeof(float));

    // 0) transpose x to [N, Cin]
    {
        dim3 blk(32, 8);
        int grid = (N + 31) / 32;
        transpose_kernel<<<grid, blk>>>(data_in, N);
    }
    // 1) gather + GEMM
    conv_kernel<<<296, 256, WELEMS * sizeof(float)>>>(neigh, weight, N);
    // 2) BN stats
    stats_kernel<<<COUT, 512>>>(gamma, beta, N);
    // 3) normalize
    {
        int total4 = (COUT * N) / 4;
        int grid = (total4 + 255) / 256;
        norm_kernel<<<grid, 256>>>(out, N);
    }
}

// round 3
// speedup vs baseline: 1.7915x; 1.7915x over previous
#include <cuda_runtime.h>
#include <cstdint>

#define CIN     32
#define COUT    32
#define KTAP    27
#define THREADS 256
#define NWARP   8
#define TILE_NODES 256          // 8 warps * 32 nodes
#define MAX_N   131072
#define BN_EPS  1e-3f

#define W_TILE  4096            // one tap's B tile: 32 rows x 128B
#define W_BYTES (KTAP * W_TILE) // 110592
#define ABUF    4096            // per-warp A buffer: 32 rows x 128B
#define NBUF    3
#define DYN_SMEM (1024 + W_BYTES + NWARP * NBUF * ABUF)   // 209920

// ---------------- device scratch ----------------
__device__ __align__(128) float g_xT[(size_t)MAX_N * CIN];   // x: [N][32] cin-PERMUTED
__device__ __align__(128) float g_wpre[KTAP * 1024];         // pre-swizzled, tf32-rounded B tiles
__device__ __align__(128) float g_y[(size_t)COUT * MAX_N];   // pre-BN result [Cout][N]
__device__ float g_params[2 * COUT];

// cin permutation: storage float f (0..31) within a node row <-> original cin.
// f = s2*16 + tig*4 + e ; cin = 16*s2 + 8*(e>>1) + 4*(e&1) + tig
static __device__ __forceinline__ int cin_of_f(int f) {
    int s2 = f >> 4, tig = (f >> 2) & 3, e = f & 3;
    return 16 * s2 + 8 * (e >> 1) + 4 * (e & 1) + tig;
}

// ---------------- PTX helpers ----------------
static __device__ __forceinline__ uint32_t smem_u32(const void* p) {
    uint32_t a;
    asm("{ .reg .u64 t; cvta.to.shared.u64 t, %1; cvt.u32.u64 %0, t; }" : "=r"(a) : "l"(p));
    return a;
}
static __device__ __forceinline__ void cp16(uint32_t dst, const void* src) {
    asm volatile("cp.async.cg.shared.global [%0], [%1], 16;" :: "r"(dst), "l"(src) : "memory");
}
#define CP_COMMIT() asm volatile("cp.async.commit_group;" ::: "memory")

static __device__ __forceinline__ void lds4f(float& x, float& y, float& z, float& w, uint32_t a) {
    asm volatile("ld.shared.v4.f32 {%0,%1,%2,%3}, [%4];"
                 : "=f"(x), "=f"(y), "=f"(z), "=f"(w) : "r"(a));
}
static __device__ __forceinline__ void lds4u(uint32_t& x, uint32_t& y, uint32_t& z, uint32_t& w,
                                             uint32_t a) {
    asm volatile("ld.shared.v4.b32 {%0,%1,%2,%3}, [%4];"
                 : "=r"(x), "=r"(y), "=r"(z), "=r"(w) : "r"(a));
}
static __device__ __forceinline__ uint32_t tf32_rna(float v) {
    uint32_t r;
    asm("cvt.rna.tf32.f32 %0, %1;" : "=r"(r) : "f"(v));
    return r;
}
static __device__ __forceinline__ void mma8(float* c, uint32_t a0, uint32_t a1, uint32_t a2,
                                            uint32_t a3, uint32_t b0, uint32_t b1) {
    asm volatile(
        "mma.sync.aligned.m16n8k8.row.col.f32.tf32.tf32.f32 "
        "{%0,%1,%2,%3}, {%4,%5,%6,%7}, {%8,%9}, {%0,%1,%2,%3};"
        : "+f"(c[0]), "+f"(c[1]), "+f"(c[2]), "+f"(c[3])
        : "r"(a0), "r"(a1), "r"(a2), "r"(a3), "r"(b0), "r"(b1));
}

// ---------------- kernel 0: transpose + cin-permute: [Cin,N] -> [N][32] ----------------
__global__ void transpose_kernel(const float* __restrict__ in, int N) {
    __shared__ float tile[32][33];
    int nb = blockIdx.x * 32;
    int tx = threadIdx.x, ty = threadIdx.y;
#pragma unroll
    for (int j = 0; j < 4; ++j) {
        int c = ty + j * 8, n = nb + tx;
        if (n < N) tile[c][tx] = in[(size_t)c * N + n];
    }
    __syncthreads();
    int cm = cin_of_f(tx);
#pragma unroll
    for (int j = 0; j < 4; ++j) {
        int nl = ty + j * 8, n = nb + nl;
        if (n < N) g_xT[(size_t)n * CIN + tx] = tile[cm][nl];
    }
}

// ---------------- kernel 1: weight prep (transpose + permute + swizzle + tf32 RNA) -------
__global__ void wprep_kernel(const float* __restrict__ w) {
    int i = blockIdx.x * blockDim.x + threadIdx.x;
    if (i >= KTAP * 1024) return;
    int k = i >> 10, r = i & 1023;
    int n = r >> 5, f = r & 31;          // n = cout row, f = storage float
    int chunk = f >> 2, e = f & 3;
    int cin = cin_of_f(f);
    float v = w[((size_t)k * CIN + cin) * COUT + n];
    uint32_t bits = tf32_rna(v);         // pre-round to tf32 (RNA, unbiased)
    int cs = chunk ^ (n & 7);            // 16B-chunk swizzle keyed by row
    g_wpre[k * 1024 + n * 32 + cs * 4 + e] = __uint_as_float(bits);
}

// ---------------- kernel 2: gather + mma.sync tf32 conv ----------------
__global__ void __launch_bounds__(THREADS)
conv_mma_kernel(const int* __restrict__ neigh, int N, int ntiles) {
    extern __shared__ char dsm[];
    const int tid  = threadIdx.x;
    const int warp = tid >> 5, lane = tid & 31;
    const int gid  = lane >> 2, tig = lane & 3;

    const uint32_t sbase = (smem_u32(dsm) + 1023u) & ~1023u;
    const uint32_t wbase = sbase;
    const uint32_t abase = sbase + W_BYTES + (uint32_t)warp * (NBUF * ABUF);

    // ---- load all 27 pre-swizzled B tiles (one time) ----
    for (int i = tid; i < W_BYTES / 16; i += THREADS)
        cp16(wbase + i * 16, reinterpret_cast<const char*>(g_wpre) + i * 16);
    CP_COMMIT();
    asm volatile("cp.async.wait_group 0;" ::: "memory");
    __syncthreads();

    for (int t = blockIdx.x; t < ntiles; t += gridDim.x) {
        const int tbase = t * TILE_NODES;
        const int mynode = tbase + (warp << 5) + lane;   // row `lane` of my A buffers

        float acc[2][4][4];
#pragma unroll
        for (int mt = 0; mt < 2; ++mt)
#pragma unroll
            for (int nt = 0; nt < 4; ++nt)
#pragma unroll
                for (int q = 0; q < 4; ++q) acc[mt][nt][q] = 0.f;

        const int sw = lane & 7;
        // prologue: gather taps 0..2
#pragma unroll
        for (int k = 0; k < NBUF; ++k) {
            int idx = (mynode < N) ? neigh[(size_t)mynode * KTAP + k] : 0;
            const char* src = reinterpret_cast<const char*>(g_xT) + (size_t)idx * 128;
            uint32_t dst = abase + (uint32_t)k * ABUF + lane * 128;
#pragma unroll
            for (int c = 0; c < 8; ++c) cp16(dst + ((c ^ sw) << 4), src + (c << 4));
            CP_COMMIT();
        }

        int b = 0;
#pragma unroll 1
        for (int k = 0; k < KTAP; ++k) {
            if (k < KTAP - 2)      asm volatile("cp.async.wait_group 2;" ::: "memory");
            else if (k == KTAP - 2) asm volatile("cp.async.wait_group 1;" ::: "memory");
            else                    asm volatile("cp.async.wait_group 0;" ::: "memory");
            __syncwarp();

            const uint32_t abuf = abase + (uint32_t)b * ABUF;
            const uint32_t wtap = wbase + (uint32_t)k * W_TILE;
#pragma unroll
            for (int s2 = 0; s2 < 2; ++s2) {
                const uint32_t ch = (uint32_t)((((s2 << 2) | tig) ^ gid) << 4);
                uint32_t B0[4], B1[4], B2[4], B3[4];
#pragma unroll
                for (int nt = 0; nt < 4; ++nt)
                    lds4u(B0[nt], B1[nt], B2[nt], B3[nt],
                          wtap + (uint32_t)((nt * 8 + gid) * 128) + ch);
#pragma unroll
                for (int mt = 0; mt < 2; ++mt) {
                    float ax, ay, az, aw, ox, oy, oz, ow;
                    lds4f(ax, ay, az, aw, abuf + (uint32_t)((mt * 16 + gid) * 128) + ch);
                    lds4f(ox, oy, oz, ow, abuf + (uint32_t)((mt * 16 + gid + 8) * 128) + ch);
                    // split each A value: hi = rna_tf32, lo = residual
                    uint32_t hx = tf32_rna(ax), hy = tf32_rna(ay), hz = tf32_rna(az),
                             hw = tf32_rna(aw);
                    uint32_t gx = tf32_rna(ox), gy = tf32_rna(oy), gz = tf32_rna(oz),
                             gw = tf32_rna(ow);
                    uint32_t lx = __float_as_uint(ax - __uint_as_float(hx));
                    uint32_t ly = __float_as_uint(ay - __uint_as_float(hy));
                    uint32_t lz = __float_as_uint(az - __uint_as_float(hz));
                    uint32_t lw = __float_as_uint(aw - __uint_as_float(hw));
                    uint32_t mx = __float_as_uint(ox - __uint_as_float(gx));
                    uint32_t my = __float_as_uint(oy - __uint_as_float(gy));
                    uint32_t mz = __float_as_uint(oz - __uint_as_float(gz));
                    uint32_t mw = __float_as_uint(ow - __uint_as_float(gw));
#pragma unroll
                    for (int nt = 0; nt < 4; ++nt) {
                        // step even (cols from .x/.y)
                        mma8(acc[mt][nt], hx, gx, hy, gy, B0[nt], B1[nt]);
                        mma8(acc[mt][nt], lx, mx, ly, my, B0[nt], B1[nt]);
                        // step odd (cols from .z/.w)
                        mma8(acc[mt][nt], hz, gz, hw, gw, B2[nt], B3[nt]);
                        mma8(acc[mt][nt], lz, mz, lw, mw, B2[nt], B3[nt]);
                    }
                }
            }

            if (k + NBUF < KTAP) {
                __syncwarp();
                int idx = (mynode < N) ? neigh[(size_t)mynode * KTAP + (k + NBUF)] : 0;
                const char* src = reinterpret_cast<const char*>(g_xT) + (size_t)idx * 128;
                uint32_t dst = abuf + lane * 128;
#pragma unroll
                for (int c = 0; c < 8; ++c) cp16(dst + ((c ^ sw) << 4), src + (c << 4));
                CP_COMMIT();
            }
            b = (b == NBUF - 1) ? 0 : b + 1;
        }

        // epilogue: direct scatter-store (sector-perfect)
#pragma unroll
        for (int mt = 0; mt < 2; ++mt) {
            int node = tbase + (warp << 5) + (mt << 4) + gid;
#pragma unroll
            for (int nt = 0; nt < 4; ++nt) {
                int cb = (nt << 3) + (tig << 1);
                if (node < N) {
                    g_y[(size_t)cb * N + node]       = acc[mt][nt][0];
                    g_y[(size_t)(cb + 1) * N + node] = acc[mt][nt][1];
                }
                if (node + 8 < N) {
                    g_y[(size_t)cb * N + node + 8]       = acc[mt][nt][2];
                    g_y[(size_t)(cb + 1) * N + node + 8] = acc[mt][nt][3];
                }
            }
        }
    }
}

// ---------------- kernel 3: BN stats -> scale/shift ----------------
__global__ void stats_kernel(const float* __restrict__ gamma,
                             const float* __restrict__ beta, int N) {
    const int d = blockIdx.x;
    const float* yd = g_y + (size_t)d * N;
    float s = 0.f, q = 0.f;
    for (int i = threadIdx.x; i < N; i += blockDim.x) {
        float v = yd[i];
        s += v; q += v * v;
    }
#pragma unroll
    for (int o = 16; o; o >>= 1) {
        s += __shfl_xor_sync(~0u, s, o);
        q += __shfl_xor_sync(~0u, q, o);
    }
    __shared__ float ss[32], sq[32];
    int wid = threadIdx.x >> 5, lane = threadIdx.x & 31;
    if (lane == 0) { ss[wid] = s; sq[wid] = q; }
    __syncthreads();
    if (threadIdx.x < 32) {
        int nw = blockDim.x >> 5;
        s = (threadIdx.x < nw) ? ss[threadIdx.x] : 0.f;
        q = (threadIdx.x < nw) ? sq[threadIdx.x] : 0.f;
#pragma unroll
        for (int o = 16; o; o >>= 1) {
            s += __shfl_xor_sync(~0u, s, o);
            q += __shfl_xor_sync(~0u, q, o);
        }
        if (threadIdx.x == 0) {
            float mean = s / (float)N;
            float var  = q / (float)N - mean * mean;
            float inv  = rsqrtf(var + BN_EPS);
            float sc   = gamma[d] * inv;
            g_params[d]        = sc;
            g_params[COUT + d] = beta[d] - mean * sc;
        }
    }
}

// ---------------- kernel 4: normalize + write output ----------------
__global__ void norm_kernel(float* __restrict__ out, int N) {
    int i = blockIdx.x * blockDim.x + threadIdx.x;
    int total4 = (COUT * N) >> 2;
    if (i >= total4) return;
    int d = (i << 2) / N;
    float4 v = reinterpret_cast<const float4*>(g_y)[i];
    float sc = g_params[d], sh = g_params[COUT + d];
    v.x = v.x * sc + sh;
    v.y = v.y * sc + sh;
    v.z = v.z * sc + sh;
    v.w = v.w * sc + sh;
    reinterpret_cast<float4*>(out)[i] = v;
}

// ---------------- launch ----------------
extern "C" void kernel_launch(void* const* d_in, const int* in_sizes, int n_in,
                              void* d_out, int out_size) {
    const float* data_in = (const float*)d_in[0];   // [1, Cin, N, 1]
    const int*   neigh   = (const int*)d_in[1];     // [N, 27]
    const float* weight  = (const float*)d_in[2];   // [27, Cin, Cout]
    const float* gamma   = (const float*)d_in[3];
    const float* beta    = (const float*)d_in[4];
    float*       out     = (float*)d_out;

    const int N = in_sizes[0] / CIN;
    const int ntiles = (N + TILE_NODES - 1) / TILE_NODES;

    int dev = 0, nsm = 148;
    cudaGetDevice(&dev);
    cudaDeviceGetAttribute(&nsm, cudaDevAttrMultiProcessorCount, dev);
    if (nsm <= 0) nsm = 148;
    int grid = (ntiles < nsm) ? ntiles : nsm;

    cudaFuncSetAttribute(conv_mma_kernel,
                         cudaFuncAttributeMaxDynamicSharedMemorySize, DYN_SMEM);

    {
        dim3 blk(32, 8);
        transpose_kernel<<<(N + 31) / 32, blk>>>(data_in, N);
    }
    wprep_kernel<<<(KTAP * 1024 + 255) / 256, 256>>>(weight);

    conv_mma_kernel<<<grid, THREADS, DYN_SMEM>>>(neigh, N, ntiles);

    stats_kernel<<<COUT, 512>>>(gamma, beta, N);
    {
        int total4 = (COUT * N) / 4;
        norm_kernel<<<(total4 + 255) / 256, 256>>>(out, N);
    }
}

// round 4
// speedup vs baseline: 2.2948x; 1.2809x over previous
#include <cuda_runtime.h>
#include <cstdint>

#define CIN     32
#define COUT    32
#define KTAP    27
#define THREADS 256
#define NWARP   8
#define TILE_NODES 256          // 8 warps * 32 nodes
#define MAX_N   131072
#define BN_EPS  1e-3f

#define W_TILE  4096            // one tap's B tile: 32 rows x 128B
#define W_BYTES (KTAP * W_TILE) // 110592
#define ABUF    4096            // per-warp A buffer: 32 rows x 128B
#define NBUF    3
#define DYN_SMEM (1024 + W_BYTES + NWARP * NBUF * ABUF)   // 209920

// ---------------- device scratch ----------------
__device__ __align__(128) float g_xT[(size_t)MAX_N * CIN];   // x: [N][32] cin-PERMUTED
__device__ __align__(128) float g_wpre[KTAP * 1024];         // pre-swizzled, tf32-rounded B tiles
__device__ __align__(128) float g_y[(size_t)COUT * MAX_N];   // pre-BN result [Cout][N]
__device__ float g_sum[COUT];                                // channel sums (atomic)
__device__ float g_sq[COUT];                                 // channel sum-of-squares (atomic)
__device__ float g_params[2 * COUT];

// cin permutation: storage float f (0..31) within a node row <-> original cin.
// f = s2*16 + tig*4 + e ; cin = 16*s2 + 8*(e>>1) + 4*(e&1) + tig
static __device__ __forceinline__ int cin_of_f(int f) {
    int s2 = f >> 4, tig = (f >> 2) & 3, e = f & 3;
    return 16 * s2 + 8 * (e >> 1) + 4 * (e & 1) + tig;
}

// ---------------- PTX helpers ----------------
static __device__ __forceinline__ uint32_t smem_u32(const void* p) {
    uint32_t a;
    asm("{ .reg .u64 t; cvta.to.shared.u64 t, %1; cvt.u32.u64 %0, t; }" : "=r"(a) : "l"(p));
    return a;
}
static __device__ __forceinline__ void cp16(uint32_t dst, const void* src) {
    asm volatile("cp.async.cg.shared.global [%0], [%1], 16;" :: "r"(dst), "l"(src) : "memory");
}
#define CP_COMMIT() asm volatile("cp.async.commit_group;" ::: "memory")

static __device__ __forceinline__ void lds4f(float& x, float& y, float& z, float& w, uint32_t a) {
    asm volatile("ld.shared.v4.f32 {%0,%1,%2,%3}, [%4];"
                 : "=f"(x), "=f"(y), "=f"(z), "=f"(w) : "r"(a));
}
static __device__ __forceinline__ void lds4u(uint32_t& x, uint32_t& y, uint32_t& z, uint32_t& w,
                                             uint32_t a) {
    asm volatile("ld.shared.v4.b32 {%0,%1,%2,%3}, [%4];"
                 : "=r"(x), "=r"(y), "=r"(z), "=r"(w) : "r"(a));
}
static __device__ __forceinline__ uint32_t tf32_rna(float v) {
    uint32_t r;
    asm("cvt.rna.tf32.f32 %0, %1;" : "=r"(r) : "f"(v));
    return r;
}
static __device__ __forceinline__ void mma8(float* c, uint32_t a0, uint32_t a1, uint32_t a2,
                                            uint32_t a3, uint32_t b0, uint32_t b1) {
    asm volatile(
        "mma.sync.aligned.m16n8k8.row.col.f32.tf32.tf32.f32 "
        "{%0,%1,%2,%3}, {%4,%5,%6,%7}, {%8,%9}, {%0,%1,%2,%3};"
        : "+f"(c[0]), "+f"(c[1]), "+f"(c[2]), "+f"(c[3])
        : "r"(a0), "r"(a1), "r"(a2), "r"(a3), "r"(b0), "r"(b1));
}

// ---------------- kernel 0a: zero the stat accumulators ----------------
__global__ void init_kernel() {
    if (threadIdx.x < COUT) {
        g_sum[threadIdx.x] = 0.f;
        g_sq[threadIdx.x]  = 0.f;
    }
}

// ---------------- kernel 0: transpose + cin-permute: [Cin,N] -> [N][32] ----------------
__global__ void transpose_kernel(const float* __restrict__ in, int N) {
    __shared__ float tile[32][33];
    int nb = blockIdx.x * 32;
    int tx = threadIdx.x, ty = threadIdx.y;
#pragma unroll
    for (int j = 0; j < 4; ++j) {
        int c = ty + j * 8, n = nb + tx;
        if (n < N) tile[c][tx] = in[(size_t)c * N + n];
    }
    __syncthreads();
    int cm = cin_of_f(tx);
#pragma unroll
    for (int j = 0; j < 4; ++j) {
        int nl = ty + j * 8, n = nb + nl;
        if (n < N) g_xT[(size_t)n * CIN + tx] = tile[cm][nl];
    }
}

// ---------------- kernel 1: weight prep (transpose + permute + swizzle + tf32 RNA) -------
__global__ void wprep_kernel(const float* __restrict__ w) {
    int i = blockIdx.x * blockDim.x + threadIdx.x;
    if (i >= KTAP * 1024) return;
    int k = i >> 10, r = i & 1023;
    int n = r >> 5, f = r & 31;          // n = cout row, f = storage float
    int chunk = f >> 2, e = f & 3;
    int cin = cin_of_f(f);
    float v = w[((size_t)k * CIN + cin) * COUT + n];
    uint32_t bits = tf32_rna(v);         // pre-round to tf32 (RNA, unbiased)
    int cs = chunk ^ (n & 7);            // 16B-chunk swizzle keyed by row
    g_wpre[k * 1024 + n * 32 + cs * 4 + e] = __uint_as_float(bits);
}

// ---------------- kernel 2: gather + mma.sync tf32 conv + fused BN stats ----------------
__global__ void __launch_bounds__(THREADS)
conv_mma_kernel(const int* __restrict__ neigh, int N, int ntiles) {
    extern __shared__ char dsm[];
    __shared__ float s_sum[COUT], s_sq[COUT];
    const int tid  = threadIdx.x;
    const int warp = tid >> 5, lane = tid & 31;
    const int gid  = lane >> 2, tig = lane & 3;

    const uint32_t sbase = (smem_u32(dsm) + 1023u) & ~1023u;
    const uint32_t wbase = sbase;
    const uint32_t abase = sbase + W_BYTES + (uint32_t)warp * (NBUF * ABUF);

    if (tid < COUT) { s_sum[tid] = 0.f; s_sq[tid] = 0.f; }

    // ---- load all 27 pre-swizzled B tiles (one time) ----
    for (int i = tid; i < W_BYTES / 16; i += THREADS)
        cp16(wbase + i * 16, reinterpret_cast<const char*>(g_wpre) + i * 16);
    CP_COMMIT();
    asm volatile("cp.async.wait_group 0;" ::: "memory");
    __syncthreads();

    // per-thread BN-stat accumulators: channels cb(nt,tig)=nt*8+tig*2 + {0,1}
    float rs[4][2], rq[4][2];
#pragma unroll
    for (int nt = 0; nt < 4; ++nt) {
        rs[nt][0] = rs[nt][1] = 0.f;
        rq[nt][0] = rq[nt][1] = 0.f;
    }

    for (int t = blockIdx.x; t < ntiles; t += gridDim.x) {
        const int tbase = t * TILE_NODES;
        const int mynode = tbase + (warp << 5) + lane;   // row `lane` of my A buffers

        float acc[2][4][4];
#pragma unroll
        for (int mt = 0; mt < 2; ++mt)
#pragma unroll
            for (int nt = 0; nt < 4; ++nt)
#pragma unroll
                for (int q = 0; q < 4; ++q) acc[mt][nt][q] = 0.f;

        const int sw = lane & 7;
        // prologue: gather taps 0..2
#pragma unroll
        for (int k = 0; k < NBUF; ++k) {
            int idx = (mynode < N) ? neigh[(size_t)mynode * KTAP + k] : 0;
            const char* src = reinterpret_cast<const char*>(g_xT) + (size_t)idx * 128;
            uint32_t dst = abase + (uint32_t)k * ABUF + lane * 128;
#pragma unroll
            for (int c = 0; c < 8; ++c) cp16(dst + ((c ^ sw) << 4), src + (c << 4));
            CP_COMMIT();
        }

        int b = 0;
#pragma unroll 1
        for (int k = 0; k < KTAP; ++k) {
            if (k < KTAP - 2)       asm volatile("cp.async.wait_group 2;" ::: "memory");
            else if (k == KTAP - 2) asm volatile("cp.async.wait_group 1;" ::: "memory");
            else                    asm volatile("cp.async.wait_group 0;" ::: "memory");
            __syncwarp();

            const uint32_t abuf = abase + (uint32_t)b * ABUF;
            const uint32_t wtap = wbase + (uint32_t)k * W_TILE;
#pragma unroll
            for (int s2 = 0; s2 < 2; ++s2) {
                const uint32_t ch = (uint32_t)((((s2 << 2) | tig) ^ gid) << 4);
                uint32_t B0[4], B1[4], B2[4], B3[4];
#pragma unroll
                for (int nt = 0; nt < 4; ++nt)
                    lds4u(B0[nt], B1[nt], B2[nt], B3[nt],
                          wtap + (uint32_t)((nt * 8 + gid) * 128) + ch);
#pragma unroll
                for (int mt = 0; mt < 2; ++mt) {
                    float ax, ay, az, aw, ox, oy, oz, ow;
                    lds4f(ax, ay, az, aw, abuf + (uint32_t)((mt * 16 + gid) * 128) + ch);
                    lds4f(ox, oy, oz, ow, abuf + (uint32_t)((mt * 16 + gid + 8) * 128) + ch);
                    // split each A value: hi = rna_tf32, lo = residual
                    uint32_t hx = tf32_rna(ax), hy = tf32_rna(ay), hz = tf32_rna(az),
                             hw = tf32_rna(aw);
                    uint32_t gx = tf32_rna(ox), gy = tf32_rna(oy), gz = tf32_rna(oz),
                             gw = tf32_rna(ow);
                    uint32_t lx = __float_as_uint(ax - __uint_as_float(hx));
                    uint32_t ly = __float_as_uint(ay - __uint_as_float(hy));
                    uint32_t lz = __float_as_uint(az - __uint_as_float(hz));
                    uint32_t lw = __float_as_uint(aw - __uint_as_float(hw));
                    uint32_t mx = __float_as_uint(ox - __uint_as_float(gx));
                    uint32_t my = __float_as_uint(oy - __uint_as_float(gy));
                    uint32_t mz = __float_as_uint(oz - __uint_as_float(gz));
                    uint32_t mw = __float_as_uint(ow - __uint_as_float(gw));
#pragma unroll
                    for (int nt = 0; nt < 4; ++nt) {
                        mma8(acc[mt][nt], hx, gx, hy, gy, B0[nt], B1[nt]);
                        mma8(acc[mt][nt], lx, mx, ly, my, B0[nt], B1[nt]);
                        mma8(acc[mt][nt], hz, gz, hw, gw, B2[nt], B3[nt]);
                        mma8(acc[mt][nt], lz, mz, lw, mw, B2[nt], B3[nt]);
                    }
                }
            }

            if (k + NBUF < KTAP) {
                __syncwarp();
                int idx = (mynode < N) ? neigh[(size_t)mynode * KTAP + (k + NBUF)] : 0;
                const char* src = reinterpret_cast<const char*>(g_xT) + (size_t)idx * 128;
                uint32_t dst = abuf + lane * 128;
#pragma unroll
                for (int c = 0; c < 8; ++c) cp16(dst + ((c ^ sw) << 4), src + (c << 4));
                CP_COMMIT();
            }
            b = (b == NBUF - 1) ? 0 : b + 1;
        }

        // epilogue: store y + accumulate BN stats in registers
#pragma unroll
        for (int mt = 0; mt < 2; ++mt) {
            int node = tbase + (warp << 5) + (mt << 4) + gid;
            bool v0 = (node < N), v1 = (node + 8 < N);
#pragma unroll
            for (int nt = 0; nt < 4; ++nt) {
                int cb = (nt << 3) + (tig << 1);
                if (v0) {
                    float a = acc[mt][nt][0], c = acc[mt][nt][1];
                    g_y[(size_t)cb * N + node]       = a;
                    g_y[(size_t)(cb + 1) * N + node] = c;
                    rs[nt][0] += a; rq[nt][0] += a * a;
                    rs[nt][1] += c; rq[nt][1] += c * c;
                }
                if (v1) {
                    float a = acc[mt][nt][2], c = acc[mt][nt][3];
                    g_y[(size_t)cb * N + node + 8]       = a;
                    g_y[(size_t)(cb + 1) * N + node + 8] = c;
                    rs[nt][0] += a; rq[nt][0] += a * a;
                    rs[nt][1] += c; rq[nt][1] += c * c;
                }
            }
        }
    }

    // ---- reduce BN stats: shuffle over gid, shared atomics, one global atomic per CTA ----
#pragma unroll
    for (int nt = 0; nt < 4; ++nt)
#pragma unroll
        for (int q = 0; q < 2; ++q) {
#pragma unroll
            for (int o = 4; o <= 16; o <<= 1) {
                rs[nt][q] += __shfl_xor_sync(~0u, rs[nt][q], o);
                rq[nt][q] += __shfl_xor_sync(~0u, rq[nt][q], o);
            }
        }
    if (gid == 0) {
#pragma unroll
        for (int nt = 0; nt < 4; ++nt)
#pragma unroll
            for (int q = 0; q < 2; ++q) {
                int cb = (nt << 3) + (tig << 1) + q;
                atomicAdd(&s_sum[cb], rs[nt][q]);
                atomicAdd(&s_sq[cb],  rq[nt][q]);
            }
    }
    __syncthreads();
    if (tid < COUT) {
        atomicAdd(&g_sum[tid], s_sum[tid]);
        atomicAdd(&g_sq[tid],  s_sq[tid]);
    }
}

// ---------------- kernel 3: finalize BN params ----------------
__global__ void finalize_kernel(const float* __restrict__ gamma,
                                const float* __restrict__ beta, int N) {
    int d = threadIdx.x;
    if (d < COUT) {
        float mean = g_sum[d] / (float)N;
        float var  = g_sq[d] / (float)N - mean * mean;
        float inv  = rsqrtf(var + BN_EPS);
        float sc   = gamma[d] * inv;
        g_params[d]        = sc;
        g_params[COUT + d] = beta[d] - mean * sc;
    }
}

// ---------------- kernel 4: normalize + write output ----------------
__global__ void norm_kernel(float* __restrict__ out, int N) {
    int i = blockIdx.x * blockDim.x + threadIdx.x;
    int total4 = (COUT * N) >> 2;
    if (i >= total4) return;
    int d = (i << 2) / N;
    float4 v = reinterpret_cast<const float4*>(g_y)[i];
    float sc = g_params[d], sh = g_params[COUT + d];
    v.x = v.x * sc + sh;
    v.y = v.y * sc + sh;
    v.z = v.z * sc + sh;
    v.w = v.w * sc + sh;
    reinterpret_cast<float4*>(out)[i] = v;
}

// ---------------- launch ----------------
extern "C" void kernel_launch(void* const* d_in, const int* in_sizes, int n_in,
                              void* d_out, int out_size) {
    const float* data_in = (const float*)d_in[0];   // [1, Cin, N, 1]
    const int*   neigh   = (const int*)d_in[1];     // [N, 27]
    const float* weight  = (const float*)d_in[2];   // [27, Cin, Cout]
    const float* gamma   = (const float*)d_in[3];
    const float* beta    = (const float*)d_in[4];
    float*       out     = (float*)d_out;

    const int N = in_sizes[0] / CIN;
    const int ntiles = (N + TILE_NODES - 1) / TILE_NODES;

    int dev = 0, nsm = 148;
    cudaGetDevice(&dev);
    cudaDeviceGetAttribute(&nsm, cudaDevAttrMultiProcessorCount, dev);
    if (nsm <= 0) nsm = 148;
    int grid = (ntiles < nsm) ? ntiles : nsm;

    cudaFuncSetAttribute(conv_mma_kernel,
                         cudaFuncAttributeMaxDynamicSharedMemorySize, DYN_SMEM);

    init_kernel<<<1, 64>>>();
    {
        dim3 blk(32, 8);
        transpose_kernel<<<(N + 31) / 32, blk>>>(data_in, N);
    }
    wprep_kernel<<<(KTAP * 1024 + 255) / 256, 256>>>(weight);

    conv_mma_kernel<<<grid, THREADS, DYN_SMEM>>>(neigh, N, ntiles);

    finalize_kernel<<<1, 32>>>(gamma, beta, N);
    {
        int total4 = (COUT * N) / 4;
        norm_kernel<<<(total4 + 255) / 256, 256>>>(out, N);
    }
}

// round 5
// speedup vs baseline: 3.2892x; 1.4333x over previous
#include <cuda_runtime.h>
#include <cstdint>

#define CIN     32
#define COUT    32
#define KTAP    27
#define THREADS 256
#define NWARP   8
#define TILE_NODES 256          // 8 warps * 32 nodes
#define MAX_N   131072
#define BN_EPS  1e-3f

#define W_TILE  4096            // one tap's B tile: 32 rows x 128B
#define W_BYTES (KTAP * W_TILE) // 110592
#define ABUF    4096            // per-warp A buffer: 32 rows x 128B
#define NBUF    3
#define DYN_SMEM (1024 + W_BYTES + NWARP * NBUF * ABUF)   // 209920

// ---------------- device scratch ----------------
__device__ __align__(128) float g_xT[(size_t)MAX_N * CIN];   // x: [N][32] cin-PERMUTED
__device__ __align__(128) float g_wpre[KTAP * 1024];         // pre-swizzled tf32 B tiles
__device__ __align__(128) int   g_neighT[(size_t)KTAP * MAX_N]; // neigh transposed [k][node]
__device__ __align__(128) float g_y[(size_t)COUT * MAX_N];   // pre-BN result [Cout][N]
__device__ float g_sum[COUT];
__device__ float g_sq[COUT];
__device__ float g_params[2 * COUT];

// cin permutation: storage float f (0..31) within a node row <-> original cin.
static __device__ __forceinline__ int cin_of_f(int f) {
    int s2 = f >> 4, tig = (f >> 2) & 3, e = f & 3;
    return 16 * s2 + 8 * (e >> 1) + 4 * (e & 1) + tig;
}

// ---------------- PTX helpers ----------------
static __device__ __forceinline__ uint32_t smem_u32(const void* p) {
    uint32_t a;
    asm("{ .reg .u64 t; cvta.to.shared.u64 t, %1; cvt.u32.u64 %0, t; }" : "=r"(a) : "l"(p));
    return a;
}
static __device__ __forceinline__ void cp16(uint32_t dst, const void* src) {
    asm volatile("cp.async.cg.shared.global [%0], [%1], 16;" :: "r"(dst), "l"(src) : "memory");
}
#define CP_COMMIT() asm volatile("cp.async.commit_group;" ::: "memory")

static __device__ __forceinline__ void lds4f(float& x, float& y, float& z, float& w, uint32_t a) {
    asm volatile("ld.shared.v4.f32 {%0,%1,%2,%3}, [%4];"
                 : "=f"(x), "=f"(y), "=f"(z), "=f"(w) : "r"(a));
}
static __device__ __forceinline__ void lds4u(uint32_t& x, uint32_t& y, uint32_t& z, uint32_t& w,
                                             uint32_t a) {
    asm volatile("ld.shared.v4.b32 {%0,%1,%2,%3}, [%4];"
                 : "=r"(x), "=r"(y), "=r"(z), "=r"(w) : "r"(a));
}
static __device__ __forceinline__ uint32_t tf32_rna(float v) {
    uint32_t r;
    asm("cvt.rna.tf32.f32 %0, %1;" : "=r"(r) : "f"(v));
    return r;
}
static __device__ __forceinline__ void mma8(float* c, uint32_t a0, uint32_t a1, uint32_t a2,
                                            uint32_t a3, uint32_t b0, uint32_t b1) {
    asm volatile(
        "mma.sync.aligned.m16n8k8.row.col.f32.tf32.tf32.f32 "
        "{%0,%1,%2,%3}, {%4,%5,%6,%7}, {%8,%9}, {%0,%1,%2,%3};"
        : "+f"(c[0]), "+f"(c[1]), "+f"(c[2]), "+f"(c[3])
        : "r"(a0), "r"(a1), "r"(a2), "r"(a3), "r"(b0), "r"(b1));
}

// cooperative gather: one warp fills 32 rows (128B each); each cp.async covers
// 4 rows x 8 lanes -> 4 L2 lines per instruction (vs 32 before).
static __device__ __forceinline__ void gather32(uint32_t dst_buf, int idx_reg, int lane) {
    const int rsub  = lane >> 3;       // 0..3
    const int chunk = lane & 7;        // 16B chunk within row
#pragma unroll
    for (int j = 0; j < 8; ++j) {
        int row = j * 4 + rsub;
        int src_idx = __shfl_sync(0xffffffffu, idx_reg, row);
        const char* src = reinterpret_cast<const char*>(g_xT + (size_t)src_idx * CIN)
                          + (chunk << 4);
        uint32_t dst = dst_buf + (uint32_t)(row << 7)
                       + (uint32_t)((chunk ^ (row & 7)) << 4);
        cp16(dst, src);
    }
}

// ---------------- kernel 0a: zero the stat accumulators ----------------
__global__ void init_kernel() {
    if (threadIdx.x < COUT) {
        g_sum[threadIdx.x] = 0.f;
        g_sq[threadIdx.x]  = 0.f;
    }
}

// ---------------- kernel 0: transpose + cin-permute: [Cin,N] -> [N][32] ----------------
__global__ void transpose_kernel(const float* __restrict__ in, int N) {
    __shared__ float tile[32][33];
    int nb = blockIdx.x * 32;
    int tx = threadIdx.x, ty = threadIdx.y;
#pragma unroll
    for (int j = 0; j < 4; ++j) {
        int c = ty + j * 8, n = nb + tx;
        if (n < N) tile[c][tx] = in[(size_t)c * N + n];
    }
    __syncthreads();
    int cm = cin_of_f(tx);
#pragma unroll
    for (int j = 0; j < 4; ++j) {
        int nl = ty + j * 8, n = nb + nl;
        if (n < N) g_xT[(size_t)n * CIN + tx] = tile[cm][nl];
    }
}

// ---------------- kernel 0b: transpose neigh [N][27] -> [27][N] ----------------
__global__ void neighT_kernel(const int* __restrict__ neigh, int N) {
    __shared__ int sb[NWARP][864];
    int warp = threadIdx.x >> 5, lane = threadIdx.x & 31;
    int base = (blockIdx.x * NWARP + warp) * 32;
    const long fb = (long)base * KTAP;
    const long total = (long)N * KTAP;
#pragma unroll
    for (int j = 0; j < KTAP; ++j) {
        long p = fb + j * 32 + lane;
        sb[warp][j * 32 + lane] = (p < total) ? neigh[p] : 0;
    }
    __syncwarp();
    int node = base + lane;
    if (node < N) {
#pragma unroll
        for (int k = 0; k < KTAP; ++k)
            g_neighT[(size_t)k * N + node] = sb[warp][lane * KTAP + k];  // stride-27: conflict-free
    }
}

// ---------------- kernel 1: weight prep (transpose + permute + swizzle + tf32 RNA) -------
__global__ void wprep_kernel(const float* __restrict__ w) {
    int i = blockIdx.x * blockDim.x + threadIdx.x;
    if (i >= KTAP * 1024) return;
    int k = i >> 10, r = i & 1023;
    int n = r >> 5, f = r & 31;
    int chunk = f >> 2, e = f & 3;
    int cin = cin_of_f(f);
    float v = w[((size_t)k * CIN + cin) * COUT + n];
    uint32_t bits = tf32_rna(v);
    int cs = chunk ^ (n & 7);
    g_wpre[k * 1024 + n * 32 + cs * 4 + e] = __uint_as_float(bits);
}

// ---------------- kernel 2: gather + mma.sync tf32 conv + fused BN stats ----------------
__global__ void __launch_bounds__(THREADS)
conv_mma_kernel(int N, int ntiles) {
    extern __shared__ char dsm[];
    __shared__ float s_sum[COUT], s_sq[COUT];
    const int tid  = threadIdx.x;
    const int warp = tid >> 5, lane = tid & 31;
    const int gid  = lane >> 2, tig = lane & 3;

    const uint32_t sbase = (smem_u32(dsm) + 1023u) & ~1023u;
    const uint32_t wbase = sbase;
    const uint32_t abase = sbase + W_BYTES + (uint32_t)warp * (NBUF * ABUF);

    if (tid < COUT) { s_sum[tid] = 0.f; s_sq[tid] = 0.f; }

    // ---- load all 27 pre-swizzled B tiles (one time) ----
    for (int i = tid; i < W_BYTES / 16; i += THREADS)
        cp16(wbase + i * 16, reinterpret_cast<const char*>(g_wpre) + i * 16);
    CP_COMMIT();
    asm volatile("cp.async.wait_group 0;" ::: "memory");
    __syncthreads();

    // per-thread BN-stat accumulators: channels cb(nt,tig)=nt*8+tig*2 + {0,1}
    float rs[4][2], rq[4][2];
#pragma unroll
    for (int nt = 0; nt < 4; ++nt) {
        rs[nt][0] = rs[nt][1] = 0.f;
        rq[nt][0] = rq[nt][1] = 0.f;
    }

    for (int t = blockIdx.x; t < ntiles; t += gridDim.x) {
        const int tbase  = t * TILE_NODES;
        const int base32 = tbase + (warp << 5);
        const int mynode = base32 + lane;
        const bool nvalid = (mynode < N);

        float acc[2][4][4];
#pragma unroll
        for (int mt = 0; mt < 2; ++mt)
#pragma unroll
            for (int nt = 0; nt < 4; ++nt)
#pragma unroll
                for (int q = 0; q < 4; ++q) acc[mt][nt][q] = 0.f;

        // prologue: gather taps 0..2
#pragma unroll
        for (int k = 0; k < NBUF; ++k) {
            int idx = nvalid ? g_neighT[(size_t)k * N + mynode] : 0;
            gather32(abase + (uint32_t)k * ABUF, idx, lane);
            CP_COMMIT();
        }

        int b = 0;
#pragma unroll 1
        for (int k = 0; k < KTAP; ++k) {
            if (k < KTAP - 2)       asm volatile("cp.async.wait_group 2;" ::: "memory");
            else if (k == KTAP - 2) asm volatile("cp.async.wait_group 1;" ::: "memory");
            else                    asm volatile("cp.async.wait_group 0;" ::: "memory");
            __syncwarp();

            const uint32_t abuf = abase + (uint32_t)b * ABUF;
            const uint32_t wtap = wbase + (uint32_t)k * W_TILE;
#pragma unroll
            for (int s2 = 0; s2 < 2; ++s2) {
                const uint32_t ch = (uint32_t)((((s2 << 2) | tig) ^ gid) << 4);
                uint32_t B0[4], B1[4], B2[4], B3[4];
#pragma unroll
                for (int nt = 0; nt < 4; ++nt)
                    lds4u(B0[nt], B1[nt], B2[nt], B3[nt],
                          wtap + (uint32_t)((nt * 8 + gid) * 128) + ch);
#pragma unroll
                for (int mt = 0; mt < 2; ++mt) {
                    float ax, ay, az, aw, ox, oy, oz, ow;
                    lds4f(ax, ay, az, aw, abuf + (uint32_t)((mt * 16 + gid) * 128) + ch);
                    lds4f(ox, oy, oz, ow, abuf + (uint32_t)((mt * 16 + gid + 8) * 128) + ch);
                    uint32_t hx = tf32_rna(ax), hy = tf32_rna(ay), hz = tf32_rna(az),
                             hw = tf32_rna(aw);
                    uint32_t gx = tf32_rna(ox), gy = tf32_rna(oy), gz = tf32_rna(oz),
                             gw = tf32_rna(ow);
#pragma unroll
                    for (int nt = 0; nt < 4; ++nt) {
                        mma8(acc[mt][nt], hx, gx, hy, gy, B0[nt], B1[nt]);
                        mma8(acc[mt][nt], hz, gz, hw, gw, B2[nt], B3[nt]);
                    }
                }
            }

            if (k + NBUF < KTAP) {
                __syncwarp();
                int idx = nvalid ? g_neighT[(size_t)(k + NBUF) * N + mynode] : 0;
                gather32(abuf, idx, lane);
                CP_COMMIT();
            }
            b = (b == NBUF - 1) ? 0 : b + 1;
        }

        // epilogue: store y + accumulate BN stats in registers
#pragma unroll
        for (int mt = 0; mt < 2; ++mt) {
            int node = base32 + (mt << 4) + gid;
            bool v0 = (node < N), v1 = (node + 8 < N);
#pragma unroll
            for (int nt = 0; nt < 4; ++nt) {
                int cb = (nt << 3) + (tig << 1);
                if (v0) {
                    float a = acc[mt][nt][0], c = acc[mt][nt][1];
                    g_y[(size_t)cb * N + node]       = a;
                    g_y[(size_t)(cb + 1) * N + node] = c;
                    rs[nt][0] += a; rq[nt][0] += a * a;
                    rs[nt][1] += c; rq[nt][1] += c * c;
                }
                if (v1) {
                    float a = acc[mt][nt][2], c = acc[mt][nt][3];
                    g_y[(size_t)cb * N + node + 8]       = a;
                    g_y[(size_t)(cb + 1) * N + node + 8] = c;
                    rs[nt][0] += a; rq[nt][0] += a * a;
                    rs[nt][1] += c; rq[nt][1] += c * c;
                }
            }
        }
    }

    // ---- reduce BN stats: shuffle over gid, shared atomics, one global atomic per CTA ----
#pragma unroll
    for (int nt = 0; nt < 4; ++nt)
#pragma unroll
        for (int q = 0; q < 2; ++q) {
#pragma unroll
            for (int o = 4; o <= 16; o <<= 1) {
                rs[nt][q] += __shfl_xor_sync(~0u, rs[nt][q], o);
                rq[nt][q] += __shfl_xor_sync(~0u, rq[nt][q], o);
            }
        }
    if (gid == 0) {
#pragma unroll
        for (int nt = 0; nt < 4; ++nt)
#pragma unroll
            for (int q = 0; q < 2; ++q) {
                int cb = (nt << 3) + (tig << 1) + q;
                atomicAdd(&s_sum[cb], rs[nt][q]);
                atomicAdd(&s_sq[cb],  rq[nt][q]);
            }
    }
    __syncthreads();
    if (tid < COUT) {
        atomicAdd(&g_sum[tid], s_sum[tid]);
        atomicAdd(&g_sq[tid],  s_sq[tid]);
    }
}

// ---------------- kernel 3: finalize BN params ----------------
__global__ void finalize_kernel(const float* __restrict__ gamma,
                                const float* __restrict__ beta, int N) {
    int d = threadIdx.x;
    if (d < COUT) {
        float mean = g_sum[d] / (float)N;
        float var  = g_sq[d] / (float)N - mean * mean;
        float inv  = rsqrtf(var + BN_EPS);
        float sc   = gamma[d] * inv;
        g_params[d]        = sc;
        g_params[COUT + d] = beta[d] - mean * sc;
    }
}

// ---------------- kernel 4: normalize + write output ----------------
__global__ void norm_kernel(float* __restrict__ out, int N) {
    int i = blockIdx.x * blockDim.x + threadIdx.x;
    int total4 = (COUT * N) >> 2;
    if (i >= total4) return;
    int d = (i << 2) / N;
    float4 v = reinterpret_cast<const float4*>(g_y)[i];
    float sc = g_params[d], sh = g_params[COUT + d];
    v.x = v.x * sc + sh;
    v.y = v.y * sc + sh;
    v.z = v.z * sc + sh;
    v.w = v.w * sc + sh;
    reinterpret_cast<float4*>(out)[i] = v;
}

// ---------------- launch ----------------
extern "C" void kernel_launch(void* const* d_in, const int* in_sizes, int n_in,
                              void* d_out, int out_size) {
    const float* data_in = (const float*)d_in[0];   // [1, Cin, N, 1]
    const int*   neigh   = (const int*)d_in[1];     // [N, 27]
    const float* weight  = (const float*)d_in[2];   // [27, Cin, Cout]
    const float* gamma   = (const float*)d_in[3];
    const float* beta    = (const float*)d_in[4];
    float*       out     = (float*)d_out;

    const int N = in_sizes[0] / CIN;
    const int ntiles = (N + TILE_NODES - 1) / TILE_NODES;

    int dev = 0, nsm = 148;
    cudaGetDevice(&dev);
    cudaDeviceGetAttribute(&nsm, cudaDevAttrMultiProcessorCount, dev);
    if (nsm <= 0) nsm = 148;
    int grid = (ntiles < nsm) ? ntiles : nsm;

    cudaFuncSetAttribute(conv_mma_kernel,
                         cudaFuncAttributeMaxDynamicSharedMemorySize, DYN_SMEM);

    init_kernel<<<1, 64>>>();
    {
        dim3 blk(32, 8);
        transpose_kernel<<<(N + 31) / 32, blk>>>(data_in, N);
    }
    neighT_kernel<<<(N + TILE_NODES - 1) / TILE_NODES, THREADS>>>(neigh, N);
    wprep_kernel<<<(KTAP * 1024 + 255) / 256, 256>>>(weight);

    conv_mma_kernel<<<grid, THREADS, DYN_SMEM>>>(N, ntiles);

    finalize_kernel<<<1, 32>>>(gamma, beta, N);
    {
        int total4 = (COUT * N) / 4;
        norm_kernel<<<(total4 + 255) / 256, 256>>>(out, N);
    }
}